// round 12
// baseline (speedup 1.0000x reference)
#include <cuda_runtime.h>
#include <cuda_bf16.h>
#include <math.h>

#define BB 64
#define TT 128
#define DD 64
#define HH 512
#define VV 16000
#define GG 2048           // 4*H
#define BT (BB*TT)        // 8192
#define HS (HH*BB)        // one h/c state buffer: 512*64 = 32768 floats
#define NCTA 128          // persistent scan CTAs (co-resident on 148 SMs)
#define KP3 1536          // 3*H split-K

typedef unsigned long long ull;

// ---------------- f32x2 packed helpers (scan kernel) -----------------------
__device__ __forceinline__ ull ffma2(ull a, ull b, ull c) {
    ull d; asm("fma.rn.f32x2 %0,%1,%2,%3;" : "=l"(d) : "l"(a), "l"(b), "l"(c)); return d;
}
__device__ __forceinline__ ull fadd2(ull a, ull b) {
    ull d; asm("add.rn.f32x2 %0,%1,%2;" : "=l"(d) : "l"(a), "l"(b)); return d;
}
__device__ __forceinline__ ull splat2(float x) {
    ull d; asm("mov.b64 %0,{%1,%1};" : "=l"(d) : "f"(x)); return d;
}
__device__ __forceinline__ float2 unpack2(ull v) {
    float2 r; asm("mov.b64 {%0,%1},%2;" : "=f"(r.x), "=f"(r.y) : "l"(v)); return r;
}
__device__ __forceinline__ float sigf(float x) {
    return __fdividef(1.f, 1.f + __expf(-x));
}
__device__ __forceinline__ float tanhfast(float x) {
    float e = __expf(2.f * x);
    return 1.f - __fdividef(2.f, e + 1.f);
}

// ---------------- tensor-core helpers --------------------------------------
__device__ __forceinline__ void ldsm4(unsigned* r, unsigned addr) {
    asm volatile("ldmatrix.sync.aligned.m8n8.x4.shared.b16 {%0,%1,%2,%3},[%4];"
                 : "=r"(r[0]), "=r"(r[1]), "=r"(r[2]), "=r"(r[3]) : "r"(addr));
}
__device__ __forceinline__ void mma_bf16(float* d, const unsigned* a,
                                         unsigned b0, unsigned b1) {
    asm volatile("mma.sync.aligned.m16n8k16.row.col.f32.bf16.bf16.f32 "
                 "{%0,%1,%2,%3},{%4,%5,%6,%7},{%8,%9},{%0,%1,%2,%3};"
                 : "+f"(d[0]), "+f"(d[1]), "+f"(d[2]), "+f"(d[3])
                 : "r"(a[0]), "r"(a[1]), "r"(a[2]), "r"(a[3]), "r"(b0), "r"(b1));
}

// ---------------- device scratch (allocation-free, static globals) --------
__device__ float g_xg [TT*GG*BB];              // gate pre-acts, t-major [t][4H][b]
__device__ float g_h  [2*HS];                  // h double buffer, transposed [k][b]
__device__ float g_c  [HS];                    // c state, transposed [k][b]
__device__ float g_hf [2*HS];                  // encoder final h per layer
__device__ float g_cf [2*HS];                  // encoder final c per layer
__device__ unsigned g_bar;                     // grid barrier arrive counter
__device__ unsigned g_gen;                     // grid barrier generation
__device__ __nv_bfloat16 g_Ax [BT*192];        // split embeddings [8192][3*64]
__device__ __nv_bfloat16 g_Aab[BT*KP3];        // split activations [8192][1536]
__device__ __nv_bfloat16 g_Bbf[VV*KP3];        // split weights (reused per GEMM)

// ---------------- embedding gather + split (A'-mode: hi,lo,hi) -------------
__global__ void gather_split(const int* __restrict__ batch,
                             const float* __restrict__ feat,
                             __nv_bfloat16* __restrict__ dst)
{
    int idx = blockIdx.x * 256 + threadIdx.x;   // over BT*DD
    int r = idx >> 6, k = idx & 63;
    float x = feat[batch[r] * DD + k];
    __nv_bfloat16 hi = __float2bfloat16_rn(x);
    __nv_bfloat16 lo = __float2bfloat16_rn(x - __bfloat162float(hi));
    size_t base = (size_t)r * 192;
    dst[base + k]       = hi;
    dst[base + 64 + k]  = lo;
    dst[base + 128 + k] = hi;
}

// ---------------- fp32 -> split-bf16 (B'-mode: hi,hi,lo) -------------------
__global__ void split_kernel(const float* __restrict__ src,
                             __nv_bfloat16* __restrict__ dst, int K)
{
    int idx = blockIdx.x * 256 + threadIdx.x;   // over M*K
    int m = idx / K, k = idx - m * K;
    float x = src[idx];
    __nv_bfloat16 hi = __float2bfloat16_rn(x);
    __nv_bfloat16 lo = __float2bfloat16_rn(x - __bfloat162float(hi));
    size_t base = (size_t)m * 3 * K;
    dst[base + k]         = hi;
    dst[base + K + k]     = hi;
    dst[base + 2 * K + k] = lo;
}

// ---------------- bf16 tensor-core GEMM ------------------------------------
// C[M,N] = A'[M,Kp] * B'[N,Kp]^T + bias1[n] + bias2[n]
// Tile 128x128, BK=32, 256 threads = 8 warps (2m x 4n), warp tile 64x32.
// smem XOR-swizzled 16B chunks: chunk' = chunk ^ ((row>>1)&3).
// scatter==0: C row-major; scatter==1: C[((m%T)*GG + n)*BB + m/T].
__global__ void __launch_bounds__(256) hgemm(
    const __nv_bfloat16* __restrict__ A, const __nv_bfloat16* __restrict__ B,
    float* __restrict__ C,
    const float* __restrict__ bias1, const float* __restrict__ bias2,
    int Kp, int N, int scatter)
{
    __shared__ __align__(16) __nv_bfloat16 sA[2][128 * 32];
    __shared__ __align__(16) __nv_bfloat16 sB[2][128 * 32];

    int tid = threadIdx.x;
    int m0 = blockIdx.y * 128, n0 = blockIdx.x * 128;
    int lane = tid & 31, warp = tid >> 5;
    int wm = warp >> 2, wn = warp & 3;

    int lrow = tid & 127;
    const __nv_bfloat16* src = (tid < 128)
        ? A + (size_t)(m0 + lrow) * Kp
        : B + (size_t)(n0 + lrow) * Kp;
    int swz = (lrow >> 1) & 3;

    float acc[4][4][4];
    #pragma unroll
    for (int i = 0; i < 4; i++)
        #pragma unroll
        for (int j = 0; j < 4; j++)
            #pragma unroll
            for (int r = 0; r < 4; r++) acc[i][j][r] = 0.f;

    {
        const uint4* s = (const uint4*)src;
        __nv_bfloat16* drow = ((tid < 128) ? sA[0] : sB[0]) + lrow * 32;
        #pragma unroll
        for (int c = 0; c < 4; c++) ((uint4*)drow)[c ^ swz] = s[c];
    }
    __syncthreads();

    int nk = Kp >> 5;
    for (int kt = 0; kt < nk; kt++) {
        int cur = kt & 1;
        bool hn = (kt + 1 < nk);
        uint4 v[4];
        if (hn) {
            const uint4* s = (const uint4*)(src + (kt + 1) * 32);
            #pragma unroll
            for (int c = 0; c < 4; c++) v[c] = s[c];
        }
        unsigned sa = (unsigned)__cvta_generic_to_shared(sA[cur]);
        unsigned sb = (unsigned)__cvta_generic_to_shared(sB[cur]);

        #pragma unroll
        for (int kk = 0; kk < 2; kk++) {
            unsigned afr[4][4];
            #pragma unroll
            for (int mb = 0; mb < 4; mb++) {
                int row = wm * 64 + mb * 16 + (lane & 15);
                int c = (kk * 2 + (lane >> 4)) ^ ((row >> 1) & 3);
                ldsm4(afr[mb], sa + row * 64 + c * 16);
            }
            unsigned bfr[2][4];
            #pragma unroll
            for (int nb2 = 0; nb2 < 2; nb2++) {
                int row = wn * 32 + nb2 * 16 + (lane & 7) + ((lane >> 4) << 3);
                int c = (kk * 2 + ((lane >> 3) & 1)) ^ ((row >> 1) & 3);
                ldsm4(bfr[nb2], sb + row * 64 + c * 16);
            }
            #pragma unroll
            for (int mb = 0; mb < 4; mb++)
                #pragma unroll
                for (int nb = 0; nb < 4; nb++) {
                    const unsigned* bp = &bfr[nb >> 1][(nb & 1) * 2];
                    mma_bf16(acc[mb][nb], afr[mb], bp[0], bp[1]);
                }
        }
        if (hn) {
            int nxt = cur ^ 1;
            __nv_bfloat16* drow = ((tid < 128) ? sA[nxt] : sB[nxt]) + lrow * 32;
            #pragma unroll
            for (int c = 0; c < 4; c++) ((uint4*)drow)[c ^ swz] = v[c];
            __syncthreads();
        }
    }

    #pragma unroll
    for (int nb = 0; nb < 4; nb++) {
        int col = n0 + wn * 32 + nb * 8 + (lane & 3) * 2;
        float b0 = 0.f, b1 = 0.f;
        if (bias1) { b0 += bias1[col]; b1 += bias1[col + 1]; }
        if (bias2) { b0 += bias2[col]; b1 += bias2[col + 1]; }
        #pragma unroll
        for (int mb = 0; mb < 4; mb++) {
            int row = m0 + wm * 64 + mb * 16 + (lane >> 2);
            float* d = acc[mb][nb];
            if (scatter == 0) {
                *(float2*)(C + (size_t)row * N + col) =
                    make_float2(d[0] + b0, d[1] + b1);
                *(float2*)(C + (size_t)(row + 8) * N + col) =
                    make_float2(d[2] + b0, d[3] + b1);
            } else {
                int t0 = row & (TT - 1), bb0i = row >> 7;
                int r2 = row + 8;
                int t1 = r2 & (TT - 1), bb1i = r2 >> 7;
                C[((size_t)t0 * GG + col    ) * BB + bb0i] = d[0] + b0;
                C[((size_t)t0 * GG + col + 1) * BB + bb0i] = d[1] + b1;
                C[((size_t)t1 * GG + col    ) * BB + bb1i] = d[2] + b0;
                C[((size_t)t1 * GG + col + 1) * BB + bb1i] = d[3] + b1;
            }
        }
    }
}

// ---------------- persistent LSTM layer kernel -----------------------------
// grid = 128 CTAs x 512 threads. CTA owns 4 hidden units (16 gate rows).
// Thread map: bp = tid&31 (b pair), d = (tid>>5)&3 (unit), ks = tid>>7 (K quarter).
// Whh resident in smem all 128 steps; c in registers (ks==0 threads).
// y is emitted directly as split-bf16 [hi|lo|hi] rows into the GEMM A buffer.
__global__ void __launch_bounds__(512) lstm_layer(
    const float* __restrict__ xg, const float* __restrict__ Whh,
    float* __restrict__ h, float* __restrict__ c,
    __nv_bfloat16* __restrict__ ysp)
{
    __shared__ float ws[512 * 16];        // ws[k][d*4+g], 32 KB
    __shared__ ull   red[3 * 128 * 4];    // ks=1..3 partials, 12 KB

    int tid = threadIdx.x;
    int jj0 = blockIdx.x << 2;

    for (int i = tid; i < 16 * 512; i += 512) {
        int r = i >> 9;
        int k = i & 511;
        int dd = r & 3, g = r >> 2;
        ws[k * 16 + dd * 4 + g] = Whh[((size_t)g * HH + jj0 + dd) * HH + k];
    }

    int bp = tid & 31;
    int d  = (tid >> 5) & 3;
    int ks = tid >> 7;                    // 0..3 (128 k each)
    int jj = jj0 + d;

    unsigned mygen = *(volatile unsigned*)&g_gen;

    float2 c2 = make_float2(0.f, 0.f);
    if (ks == 0) c2 = *(const float2*)&c[jj * BB + 2 * bp];
    __syncthreads();

    for (int t = 0; t < TT; t++) {
        const float* h_prev = h + (t & 1) * HS;
        float*       h_next = h + ((t + 1) & 1) * HS;

        float2 xi2, xf2, xgg2, xo2;
        if (ks == 0) {
            const float* p = xg + (size_t)t * GG * BB + 2 * bp;
            xi2  = *(const float2*)(p + (size_t)(jj         ) * BB);
            xf2  = *(const float2*)(p + (size_t)(jj + HH    ) * BB);
            xgg2 = *(const float2*)(p + (size_t)(jj + 2 * HH) * BB);
            xo2  = *(const float2*)(p + (size_t)(jj + 3 * HH) * BB);
        }

        const float2* hp = (const float2*)h_prev + (size_t)ks * 128 * 32 + bp;
        ull a01b0 = 0ull, a23b0 = 0ull, a01b1 = 0ull, a23b1 = 0ull;

        float2 hreg[8];
        #pragma unroll
        for (int u = 0; u < 8; u++) hreg[u] = hp[u * 32];

        #pragma unroll
        for (int blk = 0; blk < 16; blk++) {
            float2 hn[8];
            if (blk < 15) {
                #pragma unroll
                for (int u = 0; u < 8; u++) hn[u] = hp[((blk + 1) * 8 + u) * 32];
            }
            #pragma unroll
            for (int u = 0; u < 8; u++) {
                int k = (ks << 7) + (blk << 3) + u;
                ulonglong2 w = *(const ulonglong2*)&ws[k * 16 + d * 4];
                ull hb0 = splat2(hreg[u].x);
                ull hb1 = splat2(hreg[u].y);
                a01b0 = ffma2(w.x, hb0, a01b0);
                a23b0 = ffma2(w.y, hb0, a23b0);
                a01b1 = ffma2(w.x, hb1, a01b1);
                a23b1 = ffma2(w.y, hb1, a23b1);
            }
            #pragma unroll
            for (int u = 0; u < 8; u++) hreg[u] = hn[u];
        }

        if (ks) {
            ull* r = &red[((size_t)(((ks - 1) << 7) + (tid & 127))) * 4];
            r[0] = a01b0; r[1] = a23b0; r[2] = a01b1; r[3] = a23b1;
        }
        __syncthreads();
        if (ks == 0) {
            #pragma unroll
            for (int q = 0; q < 3; q++) {
                ull* r = &red[((size_t)((q << 7) + tid)) * 4];
                a01b0 = fadd2(a01b0, r[0]);
                a23b0 = fadd2(a23b0, r[1]);
                a01b1 = fadd2(a01b1, r[2]);
                a23b1 = fadd2(a23b1, r[3]);
            }
            float2 if0 = unpack2(a01b0);   // (i, f) b0
            float2 go0 = unpack2(a23b0);   // (g, o) b0
            float2 if1 = unpack2(a01b1);
            float2 go1 = unpack2(a23b1);

            float gi0 = sigf(if0.x + xi2.x);
            float gf0 = sigf(if0.y + xf2.x);
            float gg0 = tanhfast(go0.x + xgg2.x);
            float oo0 = sigf(go0.y + xo2.x);
            float gi1 = sigf(if1.x + xi2.y);
            float gf1 = sigf(if1.y + xf2.y);
            float gg1 = tanhfast(go1.x + xgg2.y);
            float oo1 = sigf(go1.y + xo2.y);

            c2.x = gf0 * c2.x + gi0 * gg0;
            c2.y = gf1 * c2.y + gi1 * gg1;
            float hv0 = oo0 * tanhfast(c2.x);
            float hv1 = oo1 * tanhfast(c2.y);

            *(float2*)&h_next[jj * BB + 2 * bp] = make_float2(hv0, hv1);

            // fused split-bf16 y emit: rows r = b*T + t, layout [hi|lo|hi]
            __nv_bfloat16 hi0 = __float2bfloat16_rn(hv0);
            __nv_bfloat16 lo0 = __float2bfloat16_rn(hv0 - __bfloat162float(hi0));
            __nv_bfloat16 hi1 = __float2bfloat16_rn(hv1);
            __nv_bfloat16 lo1 = __float2bfloat16_rn(hv1 - __bfloat162float(hi1));
            size_t r0 = ((size_t)(2 * bp) * TT + t) * KP3;
            size_t r1 = r0 + (size_t)TT * KP3;
            ysp[r0 + jj]        = hi0;
            ysp[r0 + HH + jj]   = lo0;
            ysp[r0 + 2*HH + jj] = hi0;
            ysp[r1 + jj]        = hi1;
            ysp[r1 + HH + jj]   = lo1;
            ysp[r1 + 2*HH + jj] = hi1;
        }
        __syncthreads();   // h/y stores + reduction reads complete

        if (tid == 0) {
            unsigned* barp = &g_bar;
            unsigned* genp = &g_gen;
            unsigned old;
            asm volatile("atom.release.gpu.global.add.u32 %0, [%1], %2;"
                         : "=r"(old) : "l"(barp), "r"(1u) : "memory");
            if (old == NCTA - 1) {
                asm volatile("st.relaxed.gpu.global.u32 [%0], %1;"
                             :: "l"(barp), "r"(0u) : "memory");
                asm volatile("red.release.gpu.global.add.u32 [%0], %1;"
                             :: "l"(genp), "r"(1u) : "memory");
            } else {
                unsigned cur;
                do {
                    asm volatile("ld.acquire.gpu.global.u32 %0, [%1];"
                                 : "=r"(cur) : "l"(genp) : "memory");
                } while (cur == mygen);
            }
            mygen++;
        }
        __syncthreads();
    }

    if (ks == 0) *(float2*)&c[jj * BB + 2 * bp] = c2;
}

// ---------------- row softmax (in-place, row buffered in dyn smem) --------
__global__ void __launch_bounds__(256) softmax_kernel(float* __restrict__ P, int N)
{
    extern __shared__ float row[];
    __shared__ float red[8];
    int tid = threadIdx.x;
    float* p = P + (size_t)blockIdx.x * N;

    float mx = -3.4e38f;
    for (int i = tid * 4; i < N; i += 1024) {
        float4 v = *(const float4*)(p + i);
        *(float4*)(row + i) = v;
        mx = fmaxf(mx, fmaxf(fmaxf(v.x, v.y), fmaxf(v.z, v.w)));
    }
    #pragma unroll
    for (int o = 16; o; o >>= 1) mx = fmaxf(mx, __shfl_xor_sync(0xffffffffu, mx, o));
    if ((tid & 31) == 0) red[tid >> 5] = mx;
    __syncthreads();
    float m = red[0];
    #pragma unroll
    for (int w = 1; w < 8; w++) m = fmaxf(m, red[w]);
    __syncthreads();

    float sum = 0.f;
    for (int i = tid * 4; i < N; i += 1024) {
        float4 v = *(float4*)(row + i);
        v.x = expf(v.x - m); v.y = expf(v.y - m);
        v.z = expf(v.z - m); v.w = expf(v.w - m);
        sum += (v.x + v.y) + (v.z + v.w);
        *(float4*)(row + i) = v;
    }
    #pragma unroll
    for (int o = 16; o; o >>= 1) sum += __shfl_xor_sync(0xffffffffu, sum, o);
    if ((tid & 31) == 0) red[tid >> 5] = sum;
    __syncthreads();
    float tot = 0.f;
    #pragma unroll
    for (int w = 0; w < 8; w++) tot += red[w];
    float inv = 1.f / tot;

    for (int i = tid * 4; i < N; i += 1024) {
        float4 v = *(float4*)(row + i);
        v.x *= inv; v.y *= inv; v.z *= inv; v.w *= inv;
        *(float4*)(p + i) = v;
    }
}

// ---------------- host orchestration --------------------------------------
extern "C" void kernel_launch(void* const* d_in, const int* in_sizes, int n_in,
                              void* d_out, int out_size)
{
    const int*   batch    = (const int*)d_in[0];
    const float* features = (const float*)d_in[1];
    const float* eWih0 = (const float*)d_in[2];
    const float* eWhh0 = (const float*)d_in[3];
    const float* ebih0 = (const float*)d_in[4];
    const float* ebhh0 = (const float*)d_in[5];
    const float* eWih1 = (const float*)d_in[6];
    const float* eWhh1 = (const float*)d_in[7];
    const float* ebih1 = (const float*)d_in[8];
    const float* ebhh1 = (const float*)d_in[9];
    const float* dWih0 = (const float*)d_in[10];
    const float* dWhh0 = (const float*)d_in[11];
    const float* dbih0 = (const float*)d_in[12];
    const float* dbhh0 = (const float*)d_in[13];
    const float* dWih1 = (const float*)d_in[14];
    const float* dWhh1 = (const float*)d_in[15];
    const float* dbih1 = (const float*)d_in[16];
    const float* dbhh1 = (const float*)d_in[17];
    const float* linW  = (const float*)d_in[18];
    const float* linb  = (const float*)d_in[19];
    float* out = (float*)d_out;

    float *gxg, *gh, *gc, *ghf, *gcf;
    __nv_bfloat16 *gAx, *gAab, *gBbf;
    cudaGetSymbolAddress((void**)&gxg, g_xg);
    cudaGetSymbolAddress((void**)&gh,  g_h);
    cudaGetSymbolAddress((void**)&gc,  g_c);
    cudaGetSymbolAddress((void**)&ghf, g_hf);
    cudaGetSymbolAddress((void**)&gcf, g_cf);
    cudaGetSymbolAddress((void**)&gAx,  g_Ax);
    cudaGetSymbolAddress((void**)&gAab, g_Aab);
    cudaGetSymbolAddress((void**)&gBbf, g_Bbf);

    cudaFuncSetAttribute(softmax_kernel,
                         cudaFuncAttributeMaxDynamicSharedMemorySize, VV * 4);

    dim3 gridG(GG / 128, BT / 128);     // xg GEMMs: [8192 x 2048]
    dim3 gridL(VV / 128, BT / 128);     // logits GEMM: [8192 x 16000]

    // embedding gather + split (used by enc0 and dec0)
    gather_split<<<(BT * DD) / 256, 256>>>(batch, features, gAx);

    // ---- encoder layer 0 ----
    split_kernel<<<(GG * DD) / 256, 256>>>(eWih0, gBbf, DD);
    hgemm<<<gridG, 256>>>(gAx, gBbf, gxg, ebih0, ebhh0, 3 * DD, GG, 1);
    cudaMemsetAsync(gh, 0, HS * sizeof(float), 0);
    cudaMemsetAsync(gc, 0, HS * sizeof(float), 0);
    lstm_layer<<<NCTA, 512>>>(gxg, eWhh0, gh, gc, gAab);
    cudaMemcpyAsync(ghf,      gh, HS * sizeof(float), cudaMemcpyDeviceToDevice, 0);
    cudaMemcpyAsync(gcf,      gc, HS * sizeof(float), cudaMemcpyDeviceToDevice, 0);

    // ---- encoder layer 1 (xg from enc0's split y) ----
    split_kernel<<<(GG * HH) / 256, 256>>>(eWih1, gBbf, HH);
    hgemm<<<gridG, 256>>>(gAab, gBbf, gxg, ebih1, ebhh1, KP3, GG, 1);
    cudaMemsetAsync(gh, 0, HS * sizeof(float), 0);
    cudaMemsetAsync(gc, 0, HS * sizeof(float), 0);
    lstm_layer<<<NCTA, 512>>>(gxg, eWhh1, gh, gc, gAab);
    cudaMemcpyAsync(ghf + HS, gh, HS * sizeof(float), cudaMemcpyDeviceToDevice, 0);
    cudaMemcpyAsync(gcf + HS, gc, HS * sizeof(float), cudaMemcpyDeviceToDevice, 0);

    // ---- decoder layer 0 (init from encoder layer-0 finals) ----
    split_kernel<<<(GG * DD) / 256, 256>>>(dWih0, gBbf, DD);
    hgemm<<<gridG, 256>>>(gAx, gBbf, gxg, dbih0, dbhh0, 3 * DD, GG, 1);
    cudaMemcpyAsync(gh, ghf,      HS * sizeof(float), cudaMemcpyDeviceToDevice, 0);
    cudaMemcpyAsync(gc, gcf,      HS * sizeof(float), cudaMemcpyDeviceToDevice, 0);
    lstm_layer<<<NCTA, 512>>>(gxg, dWhh0, gh, gc, gAab);

    // ---- decoder layer 1 (init from encoder layer-1 finals) ----
    split_kernel<<<(GG * HH) / 256, 256>>>(dWih1, gBbf, HH);
    hgemm<<<gridG, 256>>>(gAab, gBbf, gxg, dbih1, dbhh1, KP3, GG, 1);
    cudaMemcpyAsync(gh, ghf + HS, HS * sizeof(float), cudaMemcpyDeviceToDevice, 0);
    cudaMemcpyAsync(gc, gcf + HS, HS * sizeof(float), cudaMemcpyDeviceToDevice, 0);
    lstm_layer<<<NCTA, 512>>>(gxg, dWhh1, gh, gc, gAab);

    // ---- logits + softmax ----
    split_kernel<<<(VV * HH) / 256, 256>>>(linW, gBbf, HH);
    hgemm<<<gridL, 256>>>(gAab, gBbf, out, linb, (const float*)0, KP3, VV, 0);
    softmax_kernel<<<BT, 256, VV * 4>>>(out, VV);

    (void)in_sizes; (void)n_in; (void)out_size;
}

// round 13
// speedup vs baseline: 1.5106x; 1.5106x over previous
#include <cuda_runtime.h>
#include <cuda_bf16.h>
#include <math.h>

#define BB 64
#define TT 128
#define DD 64
#define HH 512
#define VV 16000
#define GG 2048           // 4*H
#define BT (BB*TT)        // 8192
#define HS (HH*BB)        // one h/c state buffer: 512*64 = 32768 floats
#define NCTA 128          // persistent scan CTAs (co-resident on 148 SMs)
#define KP3 1536          // 3*H split-K

typedef unsigned long long ull;

// ---------------- f32x2 packed helpers (scan kernel) -----------------------
__device__ __forceinline__ ull ffma2(ull a, ull b, ull c) {
    ull d; asm("fma.rn.f32x2 %0,%1,%2,%3;" : "=l"(d) : "l"(a), "l"(b), "l"(c)); return d;
}
__device__ __forceinline__ ull fadd2(ull a, ull b) {
    ull d; asm("add.rn.f32x2 %0,%1,%2;" : "=l"(d) : "l"(a), "l"(b)); return d;
}
__device__ __forceinline__ ull splat2(float x) {
    ull d; asm("mov.b64 %0,{%1,%1};" : "=l"(d) : "f"(x)); return d;
}
__device__ __forceinline__ float2 unpack2(ull v) {
    float2 r; asm("mov.b64 {%0,%1},%2;" : "=f"(r.x), "=f"(r.y) : "l"(v)); return r;
}
__device__ __forceinline__ float sigf(float x) {
    return __fdividef(1.f, 1.f + __expf(-x));
}
__device__ __forceinline__ float tanhfast(float x) {
    float e = __expf(2.f * x);
    return 1.f - __fdividef(2.f, e + 1.f);
}

// ---------------- tensor-core helpers --------------------------------------
__device__ __forceinline__ void ldsm4(unsigned* r, unsigned addr) {
    asm volatile("ldmatrix.sync.aligned.m8n8.x4.shared.b16 {%0,%1,%2,%3},[%4];"
                 : "=r"(r[0]), "=r"(r[1]), "=r"(r[2]), "=r"(r[3]) : "r"(addr));
}
__device__ __forceinline__ void mma_bf16(float* d, const unsigned* a,
                                         unsigned b0, unsigned b1) {
    asm volatile("mma.sync.aligned.m16n8k16.row.col.f32.bf16.bf16.f32 "
                 "{%0,%1,%2,%3},{%4,%5,%6,%7},{%8,%9},{%0,%1,%2,%3};"
                 : "+f"(d[0]), "+f"(d[1]), "+f"(d[2]), "+f"(d[3])
                 : "r"(a[0]), "r"(a[1]), "r"(a[2]), "r"(a[3]), "r"(b0), "r"(b1));
}

// ---------------- device scratch (allocation-free, static globals) --------
__device__ float g_xg [TT*GG*BB];              // gate pre-acts, t-major [t][4H][b]
__device__ float g_xg2[TT*GG*BB];              // dec0 gate pre-acts (overlap)
__device__ float g_y  [BT*HH];                 // layer output seq [b*T+t][H]
__device__ float g_h  [2*HS];                  // h double buffer, transposed [k][b]
__device__ float g_c  [HS];                    // c state, transposed [k][b]
__device__ float g_hf [2*HS];                  // encoder final h per layer
__device__ float g_cf [2*HS];                  // encoder final c per layer
__device__ unsigned g_bar;                     // grid barrier arrive counter
__device__ unsigned g_gen;                     // grid barrier generation
__device__ __nv_bfloat16 g_Ax [BT*192];        // split embeddings [8192][3*64]
__device__ __nv_bfloat16 g_Aab[BT*KP3];        // split activations [8192][1536]
__device__ __nv_bfloat16 g_Bw0[GG*192];        // split eWih0
__device__ __nv_bfloat16 g_Bw2[GG*192];        // split dWih0
__device__ __nv_bfloat16 g_Bw1[GG*KP3];        // split eWih1
__device__ __nv_bfloat16 g_Bw3[GG*KP3];        // split dWih1
__device__ __nv_bfloat16 g_BwL[VV*KP3];        // split linW

// ---------------- embedding gather + split (A'-mode: hi,lo,hi) -------------
__global__ void gather_split(const int* __restrict__ batch,
                             const float* __restrict__ feat,
                             __nv_bfloat16* __restrict__ dst)
{
    int idx = blockIdx.x * 256 + threadIdx.x;   // over BT*DD
    int r = idx >> 6, k = idx & 63;
    float x = feat[batch[r] * DD + k];
    __nv_bfloat16 hi = __float2bfloat16_rn(x);
    __nv_bfloat16 lo = __float2bfloat16_rn(x - __bfloat162float(hi));
    size_t base = (size_t)r * 192;
    dst[base + k]       = hi;
    dst[base + 64 + k]  = lo;
    dst[base + 128 + k] = hi;
}

// ---------------- fp32 -> split-bf16: mode0 A'=[hi,lo,hi], mode1 B'=[hi,hi,lo]
__global__ void split_kernel(const float* __restrict__ src,
                             __nv_bfloat16* __restrict__ dst, int K, int mode)
{
    int idx = blockIdx.x * 256 + threadIdx.x;   // over M*K
    int m = idx / K, k = idx - m * K;
    float x = src[idx];
    __nv_bfloat16 hi = __float2bfloat16_rn(x);
    __nv_bfloat16 lo = __float2bfloat16_rn(x - __bfloat162float(hi));
    size_t base = (size_t)m * 3 * K;
    dst[base + k] = hi;
    if (mode == 0) { dst[base + K + k] = lo; dst[base + 2 * K + k] = hi; }
    else           { dst[base + K + k] = hi; dst[base + 2 * K + k] = lo; }
}

// ---------------- bf16 tensor-core GEMM ------------------------------------
// C[M,N] = A'[M,Kp] * B'[N,Kp]^T + bias1[n] + bias2[n]
// Tile 128x128, BK=32, 256 threads = 8 warps (2m x 4n), warp tile 64x32.
// smem XOR-swizzled 16B chunks: chunk' = chunk ^ ((row>>1)&3).
// scatter==0: C row-major; scatter==1: C[((m%T)*GG + n)*BB + m/T].
__global__ void __launch_bounds__(256) hgemm(
    const __nv_bfloat16* __restrict__ A, const __nv_bfloat16* __restrict__ B,
    float* __restrict__ C,
    const float* __restrict__ bias1, const float* __restrict__ bias2,
    int Kp, int N, int scatter)
{
    __shared__ __align__(16) __nv_bfloat16 sA[2][128 * 32];
    __shared__ __align__(16) __nv_bfloat16 sB[2][128 * 32];

    int tid = threadIdx.x;
    int m0 = blockIdx.y * 128, n0 = blockIdx.x * 128;
    int lane = tid & 31, warp = tid >> 5;
    int wm = warp >> 2, wn = warp & 3;

    int lrow = tid & 127;
    const __nv_bfloat16* src = (tid < 128)
        ? A + (size_t)(m0 + lrow) * Kp
        : B + (size_t)(n0 + lrow) * Kp;
    int swz = (lrow >> 1) & 3;

    float acc[4][4][4];
    #pragma unroll
    for (int i = 0; i < 4; i++)
        #pragma unroll
        for (int j = 0; j < 4; j++)
            #pragma unroll
            for (int r = 0; r < 4; r++) acc[i][j][r] = 0.f;

    {
        const uint4* s = (const uint4*)src;
        __nv_bfloat16* drow = ((tid < 128) ? sA[0] : sB[0]) + lrow * 32;
        #pragma unroll
        for (int c = 0; c < 4; c++) ((uint4*)drow)[c ^ swz] = s[c];
    }
    __syncthreads();

    int nk = Kp >> 5;
    for (int kt = 0; kt < nk; kt++) {
        int cur = kt & 1;
        bool hn = (kt + 1 < nk);
        uint4 v[4];
        if (hn) {
            const uint4* s = (const uint4*)(src + (kt + 1) * 32);
            #pragma unroll
            for (int c = 0; c < 4; c++) v[c] = s[c];
        }
        unsigned sa = (unsigned)__cvta_generic_to_shared(sA[cur]);
        unsigned sb = (unsigned)__cvta_generic_to_shared(sB[cur]);

        #pragma unroll
        for (int kk = 0; kk < 2; kk++) {
            unsigned afr[4][4];
            #pragma unroll
            for (int mb = 0; mb < 4; mb++) {
                int row = wm * 64 + mb * 16 + (lane & 15);
                int c = (kk * 2 + (lane >> 4)) ^ ((row >> 1) & 3);
                ldsm4(afr[mb], sa + row * 64 + c * 16);
            }
            unsigned bfr[2][4];
            #pragma unroll
            for (int nb2 = 0; nb2 < 2; nb2++) {
                int row = wn * 32 + nb2 * 16 + (lane & 7) + ((lane >> 4) << 3);
                int c = (kk * 2 + ((lane >> 3) & 1)) ^ ((row >> 1) & 3);
                ldsm4(bfr[nb2], sb + row * 64 + c * 16);
            }
            #pragma unroll
            for (int mb = 0; mb < 4; mb++)
                #pragma unroll
                for (int nb = 0; nb < 4; nb++) {
                    const unsigned* bp = &bfr[nb >> 1][(nb & 1) * 2];
                    mma_bf16(acc[mb][nb], afr[mb], bp[0], bp[1]);
                }
        }
        if (hn) {
            int nxt = cur ^ 1;
            __nv_bfloat16* drow = ((tid < 128) ? sA[nxt] : sB[nxt]) + lrow * 32;
            #pragma unroll
            for (int c = 0; c < 4; c++) ((uint4*)drow)[c ^ swz] = v[c];
            __syncthreads();
        }
    }

    #pragma unroll
    for (int nb = 0; nb < 4; nb++) {
        int col = n0 + wn * 32 + nb * 8 + (lane & 3) * 2;
        float b0 = 0.f, b1 = 0.f;
        if (bias1) { b0 += bias1[col]; b1 += bias1[col + 1]; }
        if (bias2) { b0 += bias2[col]; b1 += bias2[col + 1]; }
        #pragma unroll
        for (int mb = 0; mb < 4; mb++) {
            int row = m0 + wm * 64 + mb * 16 + (lane >> 2);
            float* d = acc[mb][nb];
            if (scatter == 0) {
                *(float2*)(C + (size_t)row * N + col) =
                    make_float2(d[0] + b0, d[1] + b1);
                *(float2*)(C + (size_t)(row + 8) * N + col) =
                    make_float2(d[2] + b0, d[3] + b1);
            } else {
                int t0 = row & (TT - 1), bb0i = row >> 7;
                int r2 = row + 8;
                int t1 = r2 & (TT - 1), bb1i = r2 >> 7;
                C[((size_t)t0 * GG + col    ) * BB + bb0i] = d[0] + b0;
                C[((size_t)t0 * GG + col + 1) * BB + bb0i] = d[1] + b1;
                C[((size_t)t1 * GG + col    ) * BB + bb1i] = d[2] + b0;
                C[((size_t)t1 * GG + col + 1) * BB + bb1i] = d[3] + b1;
            }
        }
    }
}

// ---------------- persistent LSTM layer kernel (round-8 proven version) ----
// grid = 128 CTAs (co-resident), 256 threads. Each CTA owns 4 hidden units.
// Thread map: bp = tid&31 (b pair), d = (tid>>5)&3 (unit), ks = tid>>7 (K half).
// Whh resident in smem all 128 steps; c in registers (ks==0 threads).
__global__ void __launch_bounds__(256) lstm_layer(
    const float* __restrict__ xg, const float* __restrict__ Whh,
    float* __restrict__ h, float* __restrict__ c, float* __restrict__ y)
{
    __shared__ float ws[512 * 16];        // ws[k][d*4+g], 32 KB
    __shared__ ull   red[128 * 4];        // ks=1 partials, 4 KB

    int tid = threadIdx.x;
    int jj0 = blockIdx.x << 2;

    for (int i = tid; i < 16 * 512; i += 256) {
        int r = i >> 9;
        int k = i & 511;
        int dd = r & 3, g = r >> 2;
        ws[k * 16 + dd * 4 + g] = Whh[((size_t)g * HH + jj0 + dd) * HH + k];
    }

    int bp = tid & 31;
    int d  = (tid >> 5) & 3;
    int ks = tid >> 7;
    int jj = jj0 + d;

    unsigned mygen = *(volatile unsigned*)&g_gen;

    float2 c2 = make_float2(0.f, 0.f);
    if (ks == 0) c2 = *(const float2*)&c[jj * BB + 2 * bp];
    __syncthreads();

    for (int t = 0; t < TT; t++) {
        const float* h_prev = h + (t & 1) * HS;
        float*       h_next = h + ((t + 1) & 1) * HS;

        float2 xi2, xf2, xgg2, xo2;
        if (ks == 0) {
            const float* p = xg + (size_t)t * GG * BB + 2 * bp;
            xi2  = *(const float2*)(p + (size_t)(jj         ) * BB);
            xf2  = *(const float2*)(p + (size_t)(jj + HH    ) * BB);
            xgg2 = *(const float2*)(p + (size_t)(jj + 2 * HH) * BB);
            xo2  = *(const float2*)(p + (size_t)(jj + 3 * HH) * BB);
        }

        const float2* hp = (const float2*)h_prev + (size_t)ks * 256 * 32 + bp;
        ull a01b0 = 0ull, a23b0 = 0ull, a01b1 = 0ull, a23b1 = 0ull;

        float2 hreg[16];
        #pragma unroll
        for (int u = 0; u < 16; u++) hreg[u] = hp[u * 32];

        for (int kb = 0; kb < 16; kb++) {
            float2 hn[16];
            if (kb < 15) {
                #pragma unroll
                for (int u = 0; u < 16; u++) hn[u] = hp[((kb + 1) * 16 + u) * 32];
            }
            #pragma unroll
            for (int u = 0; u < 16; u++) {
                int k = (ks << 8) + (kb << 4) + u;
                ulonglong2 w = *(const ulonglong2*)&ws[k * 16 + d * 4];
                ull hb0 = splat2(hreg[u].x);
                ull hb1 = splat2(hreg[u].y);
                a01b0 = ffma2(w.x, hb0, a01b0);
                a23b0 = ffma2(w.y, hb0, a23b0);
                a01b1 = ffma2(w.x, hb1, a01b1);
                a23b1 = ffma2(w.y, hb1, a23b1);
            }
            #pragma unroll
            for (int u = 0; u < 16; u++) hreg[u] = hn[u];
        }

        if (ks == 1) {
            ull* r = &red[(tid & 127) * 4];
            r[0] = a01b0; r[1] = a23b0; r[2] = a01b1; r[3] = a23b1;
        }
        __syncthreads();
        if (ks == 0) {
            ull* r = &red[tid * 4];
            a01b0 = fadd2(a01b0, r[0]);
            a23b0 = fadd2(a23b0, r[1]);
            a01b1 = fadd2(a01b1, r[2]);
            a23b1 = fadd2(a23b1, r[3]);

            float2 if0 = unpack2(a01b0);
            float2 go0 = unpack2(a23b0);
            float2 if1 = unpack2(a01b1);
            float2 go1 = unpack2(a23b1);

            float gi0 = sigf(if0.x + xi2.x);
            float gf0 = sigf(if0.y + xf2.x);
            float gg0 = tanhfast(go0.x + xgg2.x);
            float oo0 = sigf(go0.y + xo2.x);
            float gi1 = sigf(if1.x + xi2.y);
            float gf1 = sigf(if1.y + xf2.y);
            float gg1 = tanhfast(go1.x + xgg2.y);
            float oo1 = sigf(go1.y + xo2.y);

            c2.x = gf0 * c2.x + gi0 * gg0;
            c2.y = gf1 * c2.y + gi1 * gg1;
            float hv0 = oo0 * tanhfast(c2.x);
            float hv1 = oo1 * tanhfast(c2.y);

            *(float2*)&h_next[jj * BB + 2 * bp] = make_float2(hv0, hv1);
            y[((size_t)(2 * bp    ) * TT + t) * HH + jj] = hv0;
            y[((size_t)(2 * bp + 1) * TT + t) * HH + jj] = hv1;
        }
        __syncthreads();

        if (tid == 0) {
            unsigned* barp = &g_bar;
            unsigned* genp = &g_gen;
            unsigned old;
            asm volatile("atom.release.gpu.global.add.u32 %0, [%1], %2;"
                         : "=r"(old) : "l"(barp), "r"(1u) : "memory");
            if (old == NCTA - 1) {
                asm volatile("st.relaxed.gpu.global.u32 [%0], %1;"
                             :: "l"(barp), "r"(0u) : "memory");
                asm volatile("red.release.gpu.global.add.u32 [%0], %1;"
                             :: "l"(genp), "r"(1u) : "memory");
            } else {
                unsigned cur;
                do {
                    asm volatile("ld.acquire.gpu.global.u32 %0, [%1];"
                                 : "=r"(cur) : "l"(genp) : "memory");
                } while (cur == mygen);
            }
            mygen++;
        }
        __syncthreads();
    }

    if (ks == 0) *(float2*)&c[jj * BB + 2 * bp] = c2;
}

// ---------------- row softmax (in-place, row buffered in dyn smem) --------
__global__ void __launch_bounds__(256) softmax_kernel(float* __restrict__ P, int N)
{
    extern __shared__ float row[];
    __shared__ float red[8];
    int tid = threadIdx.x;
    float* p = P + (size_t)blockIdx.x * N;

    float mx = -3.4e38f;
    for (int i = tid * 4; i < N; i += 1024) {
        float4 v = *(const float4*)(p + i);
        *(float4*)(row + i) = v;
        mx = fmaxf(mx, fmaxf(fmaxf(v.x, v.y), fmaxf(v.z, v.w)));
    }
    #pragma unroll
    for (int o = 16; o; o >>= 1) mx = fmaxf(mx, __shfl_xor_sync(0xffffffffu, mx, o));
    if ((tid & 31) == 0) red[tid >> 5] = mx;
    __syncthreads();
    float m = red[0];
    #pragma unroll
    for (int w = 1; w < 8; w++) m = fmaxf(m, red[w]);
    __syncthreads();

    float sum = 0.f;
    for (int i = tid * 4; i < N; i += 1024) {
        float4 v = *(float4*)(row + i);
        v.x = expf(v.x - m); v.y = expf(v.y - m);
        v.z = expf(v.z - m); v.w = expf(v.w - m);
        sum += (v.x + v.y) + (v.z + v.w);
        *(float4*)(row + i) = v;
    }
    #pragma unroll
    for (int o = 16; o; o >>= 1) sum += __shfl_xor_sync(0xffffffffu, sum, o);
    if ((tid & 31) == 0) red[tid >> 5] = sum;
    __syncthreads();
    float tot = 0.f;
    #pragma unroll
    for (int w = 0; w < 8; w++) tot += red[w];
    float inv = 1.f / tot;

    for (int i = tid * 4; i < N; i += 1024) {
        float4 v = *(float4*)(row + i);
        v.x *= inv; v.y *= inv; v.z *= inv; v.w *= inv;
        *(float4*)(p + i) = v;
    }
}

// ---------------- host orchestration --------------------------------------
extern "C" void kernel_launch(void* const* d_in, const int* in_sizes, int n_in,
                              void* d_out, int out_size)
{
    const int*   batch    = (const int*)d_in[0];
    const float* features = (const float*)d_in[1];
    const float* eWih0 = (const float*)d_in[2];
    const float* eWhh0 = (const float*)d_in[3];
    const float* ebih0 = (const float*)d_in[4];
    const float* ebhh0 = (const float*)d_in[5];
    const float* eWih1 = (const float*)d_in[6];
    const float* eWhh1 = (const float*)d_in[7];
    const float* ebih1 = (const float*)d_in[8];
    const float* ebhh1 = (const float*)d_in[9];
    const float* dWih0 = (const float*)d_in[10];
    const float* dWhh0 = (const float*)d_in[11];
    const float* dbih0 = (const float*)d_in[12];
    const float* dbhh0 = (const float*)d_in[13];
    const float* dWih1 = (const float*)d_in[14];
    const float* dWhh1 = (const float*)d_in[15];
    const float* dbih1 = (const float*)d_in[16];
    const float* dbhh1 = (const float*)d_in[17];
    const float* linW  = (const float*)d_in[18];
    const float* linb  = (const float*)d_in[19];
    float* out = (float*)d_out;

    float *gxg, *gxg2, *gy, *gh, *gc, *ghf, *gcf;
    __nv_bfloat16 *gAx, *gAab, *gBw0, *gBw1, *gBw2, *gBw3, *gBwL;
    cudaGetSymbolAddress((void**)&gxg,  g_xg);
    cudaGetSymbolAddress((void**)&gxg2, g_xg2);
    cudaGetSymbolAddress((void**)&gy,   g_y);
    cudaGetSymbolAddress((void**)&gh,   g_h);
    cudaGetSymbolAddress((void**)&gc,   g_c);
    cudaGetSymbolAddress((void**)&ghf,  g_hf);
    cudaGetSymbolAddress((void**)&gcf,  g_cf);
    cudaGetSymbolAddress((void**)&gAx,  g_Ax);
    cudaGetSymbolAddress((void**)&gAab, g_Aab);
    cudaGetSymbolAddress((void**)&gBw0, g_Bw0);
    cudaGetSymbolAddress((void**)&gBw1, g_Bw1);
    cudaGetSymbolAddress((void**)&gBw2, g_Bw2);
    cudaGetSymbolAddress((void**)&gBw3, g_Bw3);
    cudaGetSymbolAddress((void**)&gBwL, g_BwL);

    cudaFuncSetAttribute(softmax_kernel,
                         cudaFuncAttributeMaxDynamicSharedMemorySize, VV * 4);

    // side stream + events (created once; host-side resources only)
    static cudaStream_t s2 = 0;
    static cudaEvent_t evFork = 0, evGather = 0, evD0 = 0, evW1 = 0,
                       evW3 = 0, evLin = 0;
    if (!s2) {
        cudaStreamCreateWithFlags(&s2, cudaStreamNonBlocking);
        cudaEventCreateWithFlags(&evFork,   cudaEventDisableTiming);
        cudaEventCreateWithFlags(&evGather, cudaEventDisableTiming);
        cudaEventCreateWithFlags(&evD0,     cudaEventDisableTiming);
        cudaEventCreateWithFlags(&evW1,     cudaEventDisableTiming);
        cudaEventCreateWithFlags(&evW3,     cudaEventDisableTiming);
        cudaEventCreateWithFlags(&evLin,    cudaEventDisableTiming);
    }

    dim3 gridG(GG / 128, BT / 128);     // xg GEMMs: [8192 x 2048]
    dim3 gridL(VV / 128, BT / 128);     // logits GEMM: [8192 x 16000]

    // ---- fork side stream ----
    cudaEventRecord(evFork, 0);
    cudaStreamWaitEvent(s2, evFork, 0);

    // ---- main stream: embeddings + enc0 xg ----
    gather_split<<<(BT * DD) / 256, 256>>>(batch, features, gAx);
    cudaEventRecord(evGather, 0);
    split_kernel<<<(GG * DD) / 256, 256>>>(eWih0, gBw0, DD, 1);
    hgemm<<<gridG, 256>>>(gAx, gBw0, gxg, ebih0, ebhh0, 3 * DD, GG, 1);
    cudaMemsetAsync(gh, 0, HS * sizeof(float), 0);
    cudaMemsetAsync(gc, 0, HS * sizeof(float), 0);

    // ---- side stream: all scan-independent work (overlaps encoder scans) --
    split_kernel<<<(GG * DD) / 256, 256, 0, s2>>>(dWih0, gBw2, DD, 1);
    cudaStreamWaitEvent(s2, evGather, 0);
    hgemm<<<gridG, 256, 0, s2>>>(gAx, gBw2, gxg2, dbih0, dbhh0, 3 * DD, GG, 1);
    cudaEventRecord(evD0, s2);
    split_kernel<<<(GG * HH) / 256, 256, 0, s2>>>(eWih1, gBw1, HH, 1);
    cudaEventRecord(evW1, s2);
    split_kernel<<<(GG * HH) / 256, 256, 0, s2>>>(dWih1, gBw3, HH, 1);
    cudaEventRecord(evW3, s2);
    split_kernel<<<(VV * HH) / 256, 256, 0, s2>>>(linW, gBwL, HH, 1);
    cudaEventRecord(evLin, s2);

    // ---- encoder layer 0 scan ----
    lstm_layer<<<NCTA, 256>>>(gxg, eWhh0, gh, gc, gy);
    cudaMemcpyAsync(ghf, gh, HS * sizeof(float), cudaMemcpyDeviceToDevice, 0);
    cudaMemcpyAsync(gcf, gc, HS * sizeof(float), cudaMemcpyDeviceToDevice, 0);

    // ---- encoder layer 1 ----
    split_kernel<<<(BT * HH) / 256, 256>>>(gy, gAab, HH, 0);
    cudaStreamWaitEvent(0, evW1, 0);
    hgemm<<<gridG, 256>>>(gAab, gBw1, gxg, ebih1, ebhh1, KP3, GG, 1);
    cudaMemsetAsync(gh, 0, HS * sizeof(float), 0);
    cudaMemsetAsync(gc, 0, HS * sizeof(float), 0);
    lstm_layer<<<NCTA, 256>>>(gxg, eWhh1, gh, gc, gy);
    cudaMemcpyAsync(ghf + HS, gh, HS * sizeof(float), cudaMemcpyDeviceToDevice, 0);
    cudaMemcpyAsync(gcf + HS, gc, HS * sizeof(float), cudaMemcpyDeviceToDevice, 0);

    // ---- decoder layer 0 (xg precomputed on side stream) ----
    cudaStreamWaitEvent(0, evD0, 0);
    cudaMemcpyAsync(gh, ghf, HS * sizeof(float), cudaMemcpyDeviceToDevice, 0);
    cudaMemcpyAsync(gc, gcf, HS * sizeof(float), cudaMemcpyDeviceToDevice, 0);
    lstm_layer<<<NCTA, 256>>>(gxg2, dWhh0, gh, gc, gy);

    // ---- decoder layer 1 ----
    split_kernel<<<(BT * HH) / 256, 256>>>(gy, gAab, HH, 0);
    cudaStreamWaitEvent(0, evW3, 0);
    hgemm<<<gridG, 256>>>(gAab, gBw3, gxg, dbih1, dbhh1, KP3, GG, 1);
    cudaMemcpyAsync(gh, ghf + HS, HS * sizeof(float), cudaMemcpyDeviceToDevice, 0);
    cudaMemcpyAsync(gc, gcf + HS, HS * sizeof(float), cudaMemcpyDeviceToDevice, 0);
    lstm_layer<<<NCTA, 256>>>(gxg, dWhh1, gh, gc, gy);

    // ---- logits + softmax ----
    split_kernel<<<(BT * HH) / 256, 256>>>(gy, gAab, HH, 0);
    cudaStreamWaitEvent(0, evLin, 0);
    hgemm<<<gridL, 256>>>(gAab, gBwL, out, linb, (const float*)0, KP3, VV, 0);
    softmax_kernel<<<BT, 256, VV * 4>>>(out, VV);

    (void)in_sizes; (void)n_in; (void)out_size;
}

// round 14
// speedup vs baseline: 1.7717x; 1.1729x over previous
#include <cuda_runtime.h>
#include <cuda_bf16.h>
#include <math.h>

#define BB 64
#define TT 128
#define DD 64
#define HH 512
#define VV 16000
#define GG 2048           // 4*H
#define BT (BB*TT)        // 8192
#define HS (HH*BB)        // one h/c state buffer: 512*64 = 32768 floats
#define NCTA2 256         // scan CTAs: 2 per SM co-resident (128 unit-groups x 2 batch halves)
#define KP3 1536          // 3*H split-K

typedef unsigned long long ull;

// ---------------- f32x2 packed helpers (scan kernel) -----------------------
__device__ __forceinline__ ull ffma2(ull a, ull b, ull c) {
    ull d; asm("fma.rn.f32x2 %0,%1,%2,%3;" : "=l"(d) : "l"(a), "l"(b), "l"(c)); return d;
}
__device__ __forceinline__ ull fadd2(ull a, ull b) {
    ull d; asm("add.rn.f32x2 %0,%1,%2;" : "=l"(d) : "l"(a), "l"(b)); return d;
}
__device__ __forceinline__ ull splat2(float x) {
    ull d; asm("mov.b64 %0,{%1,%1};" : "=l"(d) : "f"(x)); return d;
}
__device__ __forceinline__ float2 unpack2(ull v) {
    float2 r; asm("mov.b64 {%0,%1},%2;" : "=f"(r.x), "=f"(r.y) : "l"(v)); return r;
}
__device__ __forceinline__ float sigf(float x) {
    return __fdividef(1.f, 1.f + __expf(-x));
}
__device__ __forceinline__ float tanhfast(float x) {
    float e = __expf(2.f * x);
    return 1.f - __fdividef(2.f, e + 1.f);
}

// ---------------- tensor-core helpers --------------------------------------
__device__ __forceinline__ void ldsm4(unsigned* r, unsigned addr) {
    asm volatile("ldmatrix.sync.aligned.m8n8.x4.shared.b16 {%0,%1,%2,%3},[%4];"
                 : "=r"(r[0]), "=r"(r[1]), "=r"(r[2]), "=r"(r[3]) : "r"(addr));
}
__device__ __forceinline__ void mma_bf16(float* d, const unsigned* a,
                                         unsigned b0, unsigned b1) {
    asm volatile("mma.sync.aligned.m16n8k16.row.col.f32.bf16.bf16.f32 "
                 "{%0,%1,%2,%3},{%4,%5,%6,%7},{%8,%9},{%0,%1,%2,%3};"
                 : "+f"(d[0]), "+f"(d[1]), "+f"(d[2]), "+f"(d[3])
                 : "r"(a[0]), "r"(a[1]), "r"(a[2]), "r"(a[3]), "r"(b0), "r"(b1));
}

// ---------------- device scratch (allocation-free, static globals) --------
__device__ float g_xg [TT*GG*BB];              // gate pre-acts, t-major [t][4H][b]
__device__ float g_y  [BT*HH];                 // layer output seq [b*T+t][H]
__device__ float g_h  [2*HS];                  // h double buffer, transposed [k][b]
__device__ float g_c  [HS];                    // c state, transposed [k][b]
__device__ float g_hf [2*HS];                  // encoder final h per layer
__device__ float g_cf [2*HS];                  // encoder final c per layer
__device__ unsigned g_bar;                     // grid barrier arrive counter
__device__ unsigned g_gen;                     // grid barrier generation
__device__ __nv_bfloat16 g_Ax [BT*192];        // split embeddings [8192][3*64]
__device__ __nv_bfloat16 g_Aab[BT*KP3];        // split activations [8192][1536]
__device__ __nv_bfloat16 g_Bbf[VV*KP3];        // split weights (reused per GEMM)

// ---------------- embedding gather + split (A'-mode: hi,lo,hi) -------------
__global__ void gather_split(const int* __restrict__ batch,
                             const float* __restrict__ feat,
                             __nv_bfloat16* __restrict__ dst)
{
    int idx = blockIdx.x * 256 + threadIdx.x;   // over BT*DD
    int r = idx >> 6, k = idx & 63;
    float x = feat[batch[r] * DD + k];
    __nv_bfloat16 hi = __float2bfloat16_rn(x);
    __nv_bfloat16 lo = __float2bfloat16_rn(x - __bfloat162float(hi));
    size_t base = (size_t)r * 192;
    dst[base + k]       = hi;
    dst[base + 64 + k]  = lo;
    dst[base + 128 + k] = hi;
}

// ---------------- fp32 -> split-bf16: mode0 A'=[hi,lo,hi], mode1 B'=[hi,hi,lo]
__global__ void split_kernel(const float* __restrict__ src,
                             __nv_bfloat16* __restrict__ dst, int K, int mode)
{
    int idx = blockIdx.x * 256 + threadIdx.x;   // over M*K
    int m = idx / K, k = idx - m * K;
    float x = src[idx];
    __nv_bfloat16 hi = __float2bfloat16_rn(x);
    __nv_bfloat16 lo = __float2bfloat16_rn(x - __bfloat162float(hi));
    size_t base = (size_t)m * 3 * K;
    dst[base + k] = hi;
    if (mode == 0) { dst[base + K + k] = lo; dst[base + 2 * K + k] = hi; }
    else           { dst[base + K + k] = hi; dst[base + 2 * K + k] = lo; }
}

// ---------------- bf16 tensor-core GEMM ------------------------------------
// C[M,N] = A'[M,Kp] * B'[N,Kp]^T + bias1[n] + bias2[n]
// Tile 128x128, BK=32, 256 threads = 8 warps (2m x 4n), warp tile 64x32.
// smem XOR-swizzled 16B chunks: chunk' = chunk ^ ((row>>1)&3).
// scatter==0: C row-major; scatter==1: C[((m%T)*GG + n)*BB + m/T].
__global__ void __launch_bounds__(256) hgemm(
    const __nv_bfloat16* __restrict__ A, const __nv_bfloat16* __restrict__ B,
    float* __restrict__ C,
    const float* __restrict__ bias1, const float* __restrict__ bias2,
    int Kp, int N, int scatter)
{
    __shared__ __align__(16) __nv_bfloat16 sA[2][128 * 32];
    __shared__ __align__(16) __nv_bfloat16 sB[2][128 * 32];

    int tid = threadIdx.x;
    int m0 = blockIdx.y * 128, n0 = blockIdx.x * 128;
    int lane = tid & 31, warp = tid >> 5;
    int wm = warp >> 2, wn = warp & 3;

    int lrow = tid & 127;
    const __nv_bfloat16* src = (tid < 128)
        ? A + (size_t)(m0 + lrow) * Kp
        : B + (size_t)(n0 + lrow) * Kp;
    int swz = (lrow >> 1) & 3;

    float acc[4][4][4];
    #pragma unroll
    for (int i = 0; i < 4; i++)
        #pragma unroll
        for (int j = 0; j < 4; j++)
            #pragma unroll
            for (int r = 0; r < 4; r++) acc[i][j][r] = 0.f;

    {
        const uint4* s = (const uint4*)src;
        __nv_bfloat16* drow = ((tid < 128) ? sA[0] : sB[0]) + lrow * 32;
        #pragma unroll
        for (int c = 0; c < 4; c++) ((uint4*)drow)[c ^ swz] = s[c];
    }
    __syncthreads();

    int nk = Kp >> 5;
    for (int kt = 0; kt < nk; kt++) {
        int cur = kt & 1;
        bool hn = (kt + 1 < nk);
        uint4 v[4];
        if (hn) {
            const uint4* s = (const uint4*)(src + (kt + 1) * 32);
            #pragma unroll
            for (int c = 0; c < 4; c++) v[c] = s[c];
        }
        unsigned sa = (unsigned)__cvta_generic_to_shared(sA[cur]);
        unsigned sb = (unsigned)__cvta_generic_to_shared(sB[cur]);

        #pragma unroll
        for (int kk = 0; kk < 2; kk++) {
            unsigned afr[4][4];
            #pragma unroll
            for (int mb = 0; mb < 4; mb++) {
                int row = wm * 64 + mb * 16 + (lane & 15);
                int c = (kk * 2 + (lane >> 4)) ^ ((row >> 1) & 3);
                ldsm4(afr[mb], sa + row * 64 + c * 16);
            }
            unsigned bfr[2][4];
            #pragma unroll
            for (int nb2 = 0; nb2 < 2; nb2++) {
                int row = wn * 32 + nb2 * 16 + (lane & 7) + ((lane >> 4) << 3);
                int c = (kk * 2 + ((lane >> 3) & 1)) ^ ((row >> 1) & 3);
                ldsm4(bfr[nb2], sb + row * 64 + c * 16);
            }
            #pragma unroll
            for (int mb = 0; mb < 4; mb++)
                #pragma unroll
                for (int nb = 0; nb < 4; nb++) {
                    const unsigned* bp = &bfr[nb >> 1][(nb & 1) * 2];
                    mma_bf16(acc[mb][nb], afr[mb], bp[0], bp[1]);
                }
        }
        if (hn) {
            int nxt = cur ^ 1;
            __nv_bfloat16* drow = ((tid < 128) ? sA[nxt] : sB[nxt]) + lrow * 32;
            #pragma unroll
            for (int c = 0; c < 4; c++) ((uint4*)drow)[c ^ swz] = v[c];
            __syncthreads();
        }
    }

    #pragma unroll
    for (int nb = 0; nb < 4; nb++) {
        int col = n0 + wn * 32 + nb * 8 + (lane & 3) * 2;
        float b0 = 0.f, b1 = 0.f;
        if (bias1) { b0 += bias1[col]; b1 += bias1[col + 1]; }
        if (bias2) { b0 += bias2[col]; b1 += bias2[col + 1]; }
        #pragma unroll
        for (int mb = 0; mb < 4; mb++) {
            int row = m0 + wm * 64 + mb * 16 + (lane >> 2);
            float* d = acc[mb][nb];
            if (scatter == 0) {
                *(float2*)(C + (size_t)row * N + col) =
                    make_float2(d[0] + b0, d[1] + b1);
                *(float2*)(C + (size_t)(row + 8) * N + col) =
                    make_float2(d[2] + b0, d[3] + b1);
            } else {
                int t0 = row & (TT - 1), bb0i = row >> 7;
                int r2 = row + 8;
                int t1 = r2 & (TT - 1), bb1i = r2 >> 7;
                C[((size_t)t0 * GG + col    ) * BB + bb0i] = d[0] + b0;
                C[((size_t)t0 * GG + col + 1) * BB + bb0i] = d[1] + b1;
                C[((size_t)t1 * GG + col    ) * BB + bb1i] = d[2] + b0;
                C[((size_t)t1 * GG + col + 1) * BB + bb1i] = d[3] + b1;
            }
        }
    }
}

// ---------------- persistent LSTM layer kernel -----------------------------
// grid = 256 CTAs (2 co-resident per SM), 256 threads.
// CTA = (unit group of 4, batch half). Thread map: bp = tid&15 (b pair within
// half), d = (tid>>4)&3 (unit), ks = tid>>6 (K quarter, 128 k each).
// Whh resident in smem all 128 steps; c in registers (ks==0 threads).
// Per-CTA L2 h-traffic is halved vs the 128-CTA version (reads only its 32 b),
// so chip-wide traffic is unchanged while warps/SMSP double (2 -> 4).
__global__ void __launch_bounds__(256, 2) lstm_layer(
    const float* __restrict__ xg, const float* __restrict__ Whh,
    float* __restrict__ h, float* __restrict__ c, float* __restrict__ y)
{
    __shared__ float ws[512 * 16];        // ws[k][d*4+g], 32 KB
    __shared__ ull   red[3 * 64 * 4];     // ks=1..3 partials, 6 KB

    int tid = threadIdx.x;
    int jj0   = (blockIdx.x >> 1) << 2;   // unit group base
    int bhalf = blockIdx.x & 1;           // batch half

    for (int i = tid; i < 16 * 512; i += 256) {
        int r = i >> 9;
        int k = i & 511;
        int dd = r & 3, g = r >> 2;
        ws[k * 16 + dd * 4 + g] = Whh[((size_t)g * HH + jj0 + dd) * HH + k];
    }

    int bp = tid & 15;                    // b-pair within half (16 pairs = 32 b)
    int d  = (tid >> 4) & 3;              // unit 0..3
    int ks = tid >> 6;                    // K quarter 0..3 (128 k each)
    int jj = jj0 + d;
    int bb = bhalf * 16 + bp;             // global b-pair index (0..31)

    unsigned mygen = *(volatile unsigned*)&g_gen;

    float2 c2 = make_float2(0.f, 0.f);
    if (ks == 0) c2 = *(const float2*)&c[jj * BB + 2 * bb];
    __syncthreads();

    for (int t = 0; t < TT; t++) {
        const float* h_prev = h + (t & 1) * HS;
        float*       h_next = h + ((t + 1) & 1) * HS;

        float2 xi2, xf2, xgg2, xo2;
        if (ks == 0) {
            const float* p = xg + (size_t)t * GG * BB + 2 * bb;
            xi2  = *(const float2*)(p + (size_t)(jj         ) * BB);
            xf2  = *(const float2*)(p + (size_t)(jj + HH    ) * BB);
            xgg2 = *(const float2*)(p + (size_t)(jj + 2 * HH) * BB);
            xo2  = *(const float2*)(p + (size_t)(jj + 3 * HH) * BB);
        }

        // this thread's K quarter (128 k), 4 gates x 2 b
        const float2* hp = (const float2*)h_prev + (size_t)ks * 128 * 32 + bb;
        ull a01b0 = 0ull, a23b0 = 0ull, a01b1 = 0ull, a23b1 = 0ull;

        float2 hreg[16];
        #pragma unroll
        for (int u = 0; u < 16; u++) hreg[u] = hp[u * 32];

        for (int kb = 0; kb < 8; kb++) {
            float2 hn[16];
            if (kb < 7) {
                #pragma unroll
                for (int u = 0; u < 16; u++) hn[u] = hp[((kb + 1) * 16 + u) * 32];
            }
            #pragma unroll
            for (int u = 0; u < 16; u++) {
                int k = (ks << 7) + (kb << 4) + u;
                ulonglong2 w = *(const ulonglong2*)&ws[k * 16 + d * 4];
                ull hb0 = splat2(hreg[u].x);
                ull hb1 = splat2(hreg[u].y);
                a01b0 = ffma2(w.x, hb0, a01b0);
                a23b0 = ffma2(w.y, hb0, a23b0);
                a01b1 = ffma2(w.x, hb1, a01b1);
                a23b1 = ffma2(w.y, hb1, a23b1);
            }
            #pragma unroll
            for (int u = 0; u < 16; u++) hreg[u] = hn[u];
        }

        if (ks) {
            ull* r = &red[(((ks - 1) << 6) + (tid & 63)) * 4];
            r[0] = a01b0; r[1] = a23b0; r[2] = a01b1; r[3] = a23b1;
        }
        __syncthreads();
        if (ks == 0) {
            #pragma unroll
            for (int q = 0; q < 3; q++) {
                ull* r = &red[((q << 6) + tid) * 4];
                a01b0 = fadd2(a01b0, r[0]);
                a23b0 = fadd2(a23b0, r[1]);
                a01b1 = fadd2(a01b1, r[2]);
                a23b1 = fadd2(a23b1, r[3]);
            }
            float2 if0 = unpack2(a01b0);   // (i, f) b0
            float2 go0 = unpack2(a23b0);   // (g, o) b0
            float2 if1 = unpack2(a01b1);
            float2 go1 = unpack2(a23b1);

            float gi0 = sigf(if0.x + xi2.x);
            float gf0 = sigf(if0.y + xf2.x);
            float gg0 = tanhfast(go0.x + xgg2.x);
            float oo0 = sigf(go0.y + xo2.x);
            float gi1 = sigf(if1.x + xi2.y);
            float gf1 = sigf(if1.y + xf2.y);
            float gg1 = tanhfast(go1.x + xgg2.y);
            float oo1 = sigf(go1.y + xo2.y);

            c2.x = gf0 * c2.x + gi0 * gg0;
            c2.y = gf1 * c2.y + gi1 * gg1;
            float hv0 = oo0 * tanhfast(c2.x);
            float hv1 = oo1 * tanhfast(c2.y);

            *(float2*)&h_next[jj * BB + 2 * bb] = make_float2(hv0, hv1);
            y[((size_t)(2 * bb    ) * TT + t) * HH + jj] = hv0;
            y[((size_t)(2 * bb + 1) * TT + t) * HH + jj] = hv1;
        }
        __syncthreads();

        if (tid == 0) {
            unsigned* barp = &g_bar;
            unsigned* genp = &g_gen;
            unsigned old;
            asm volatile("atom.release.gpu.global.add.u32 %0, [%1], %2;"
                         : "=r"(old) : "l"(barp), "r"(1u) : "memory");
            if (old == NCTA2 - 1) {
                asm volatile("st.relaxed.gpu.global.u32 [%0], %1;"
                             :: "l"(barp), "r"(0u) : "memory");
                asm volatile("red.release.gpu.global.add.u32 [%0], %1;"
                             :: "l"(genp), "r"(1u) : "memory");
            } else {
                unsigned cur;
                do {
                    asm volatile("ld.acquire.gpu.global.u32 %0, [%1];"
                                 : "=r"(cur) : "l"(genp) : "memory");
                } while (cur == mygen);
            }
            mygen++;
        }
        __syncthreads();
    }

    if (ks == 0) *(float2*)&c[jj * BB + 2 * bb] = c2;
}

// ---------------- row softmax (in-place, row buffered in dyn smem) --------
__global__ void __launch_bounds__(256) softmax_kernel(float* __restrict__ P, int N)
{
    extern __shared__ float row[];
    __shared__ float red[8];
    int tid = threadIdx.x;
    float* p = P + (size_t)blockIdx.x * N;

    float mx = -3.4e38f;
    for (int i = tid * 4; i < N; i += 1024) {
        float4 v = *(const float4*)(p + i);
        *(float4*)(row + i) = v;
        mx = fmaxf(mx, fmaxf(fmaxf(v.x, v.y), fmaxf(v.z, v.w)));
    }
    #pragma unroll
    for (int o = 16; o; o >>= 1) mx = fmaxf(mx, __shfl_xor_sync(0xffffffffu, mx, o));
    if ((tid & 31) == 0) red[tid >> 5] = mx;
    __syncthreads();
    float m = red[0];
    #pragma unroll
    for (int w = 1; w < 8; w++) m = fmaxf(m, red[w]);
    __syncthreads();

    float sum = 0.f;
    for (int i = tid * 4; i < N; i += 1024) {
        float4 v = *(float4*)(row + i);
        v.x = __expf(v.x - m); v.y = __expf(v.y - m);
        v.z = __expf(v.z - m); v.w = __expf(v.w - m);
        sum += (v.x + v.y) + (v.z + v.w);
        *(float4*)(row + i) = v;
    }
    #pragma unroll
    for (int o = 16; o; o >>= 1) sum += __shfl_xor_sync(0xffffffffu, sum, o);
    if ((tid & 31) == 0) red[tid >> 5] = sum;
    __syncthreads();
    float tot = 0.f;
    #pragma unroll
    for (int w = 0; w < 8; w++) tot += red[w];
    float inv = 1.f / tot;

    for (int i = tid * 4; i < N; i += 1024) {
        float4 v = *(float4*)(row + i);
        v.x *= inv; v.y *= inv; v.z *= inv; v.w *= inv;
        *(float4*)(p + i) = v;
    }
}

// ---------------- host orchestration (serial — nothing overlaps the scans) -
extern "C" void kernel_launch(void* const* d_in, const int* in_sizes, int n_in,
                              void* d_out, int out_size)
{
    const int*   batch    = (const int*)d_in[0];
    const float* features = (const float*)d_in[1];
    const float* eWih0 = (const float*)d_in[2];
    const float* eWhh0 = (const float*)d_in[3];
    const float* ebih0 = (const float*)d_in[4];
    const float* ebhh0 = (const float*)d_in[5];
    const float* eWih1 = (const float*)d_in[6];
    const float* eWhh1 = (const float*)d_in[7];
    const float* ebih1 = (const float*)d_in[8];
    const float* ebhh1 = (const float*)d_in[9];
    const float* dWih0 = (const float*)d_in[10];
    const float* dWhh0 = (const float*)d_in[11];
    const float* dbih0 = (const float*)d_in[12];
    const float* dbhh0 = (const float*)d_in[13];
    const float* dWih1 = (const float*)d_in[14];
    const float* dWhh1 = (const float*)d_in[15];
    const float* dbih1 = (const float*)d_in[16];
    const float* dbhh1 = (const float*)d_in[17];
    const float* linW  = (const float*)d_in[18];
    const float* linb  = (const float*)d_in[19];
    float* out = (float*)d_out;

    float *gxg, *gy, *gh, *gc, *ghf, *gcf;
    __nv_bfloat16 *gAx, *gAab, *gBbf;
    cudaGetSymbolAddress((void**)&gxg, g_xg);
    cudaGetSymbolAddress((void**)&gy,  g_y);
    cudaGetSymbolAddress((void**)&gh,  g_h);
    cudaGetSymbolAddress((void**)&gc,  g_c);
    cudaGetSymbolAddress((void**)&ghf, g_hf);
    cudaGetSymbolAddress((void**)&gcf, g_cf);
    cudaGetSymbolAddress((void**)&gAx,  g_Ax);
    cudaGetSymbolAddress((void**)&gAab, g_Aab);
    cudaGetSymbolAddress((void**)&gBbf, g_Bbf);

    cudaFuncSetAttribute(softmax_kernel,
                         cudaFuncAttributeMaxDynamicSharedMemorySize, VV * 4);

    dim3 gridG(GG / 128, BT / 128);     // xg GEMMs: [8192 x 2048]
    dim3 gridL(VV / 128, BT / 128);     // logits GEMM: [8192 x 16000]

    // embedding gather + split (used by enc0 and dec0)
    gather_split<<<(BT * DD) / 256, 256>>>(batch, features, gAx);

    // ---- encoder layer 0 ----
    split_kernel<<<(GG * DD) / 256, 256>>>(eWih0, gBbf, DD, 1);
    hgemm<<<gridG, 256>>>(gAx, gBbf, gxg, ebih0, ebhh0, 3 * DD, GG, 1);
    cudaMemsetAsync(gh, 0, HS * sizeof(float), 0);
    cudaMemsetAsync(gc, 0, HS * sizeof(float), 0);
    lstm_layer<<<NCTA2, 256>>>(gxg, eWhh0, gh, gc, gy);
    cudaMemcpyAsync(ghf,      gh, HS * sizeof(float), cudaMemcpyDeviceToDevice, 0);
    cudaMemcpyAsync(gcf,      gc, HS * sizeof(float), cudaMemcpyDeviceToDevice, 0);

    // ---- encoder layer 1 ----
    split_kernel<<<(BT * HH) / 256, 256>>>(gy, gAab, HH, 0);
    split_kernel<<<(GG * HH) / 256, 256>>>(eWih1, gBbf, HH, 1);
    hgemm<<<gridG, 256>>>(gAab, gBbf, gxg, ebih1, ebhh1, KP3, GG, 1);
    cudaMemsetAsync(gh, 0, HS * sizeof(float), 0);
    cudaMemsetAsync(gc, 0, HS * sizeof(float), 0);
    lstm_layer<<<NCTA2, 256>>>(gxg, eWhh1, gh, gc, gy);
    cudaMemcpyAsync(ghf + HS, gh, HS * sizeof(float), cudaMemcpyDeviceToDevice, 0);
    cudaMemcpyAsync(gcf + HS, gc, HS * sizeof(float), cudaMemcpyDeviceToDevice, 0);

    // ---- decoder layer 0 (init from encoder layer-0 finals) ----
    split_kernel<<<(GG * DD) / 256, 256>>>(dWih0, gBbf, DD, 1);
    hgemm<<<gridG, 256>>>(gAx, gBbf, gxg, dbih0, dbhh0, 3 * DD, GG, 1);
    cudaMemcpyAsync(gh, ghf,      HS * sizeof(float), cudaMemcpyDeviceToDevice, 0);
    cudaMemcpyAsync(gc, gcf,      HS * sizeof(float), cudaMemcpyDeviceToDevice, 0);
    lstm_layer<<<NCTA2, 256>>>(gxg, dWhh0, gh, gc, gy);

    // ---- decoder layer 1 (init from encoder layer-1 finals) ----
    split_kernel<<<(BT * HH) / 256, 256>>>(gy, gAab, HH, 0);
    split_kernel<<<(GG * HH) / 256, 256>>>(dWih1, gBbf, HH, 1);
    hgemm<<<gridG, 256>>>(gAab, gBbf, gxg, dbih1, dbhh1, KP3, GG, 1);
    cudaMemcpyAsync(gh, ghf + HS, HS * sizeof(float), cudaMemcpyDeviceToDevice, 0);
    cudaMemcpyAsync(gc, gcf + HS, HS * sizeof(float), cudaMemcpyDeviceToDevice, 0);
    lstm_layer<<<NCTA2, 256>>>(gxg, dWhh1, gh, gc, gy);

    // ---- logits + softmax ----
    split_kernel<<<(BT * HH) / 256, 256>>>(gy, gAab, HH, 0);
    split_kernel<<<(VV * HH) / 256, 256>>>(linW, gBbf, HH, 1);
    hgemm<<<gridL, 256>>>(gAab, gBbf, out, linb, (const float*)0, KP3, VV, 0);
    softmax_kernel<<<BT, 256, VV * 4>>>(out, VV);

    (void)in_sizes; (void)n_in; (void)out_size;
}